// round 13
// baseline (speedup 1.0000x reference)
#include <cuda_runtime.h>
#include <cuda_bf16.h>

// SENet gating: FULLY per-warp TMA. 128-thread blocks for packing only;
// zero __syncthreads. Each warp, independently:
//   1. lane 0: init OWN mbarrier, issue OWN 6 KB cp.async.bulk load
//      (evict_first); warp parity-waits its own barrier
//   2. segment sums (lane = row*4 + quarter, pattern (20,6,21) x 4,
//      balanced, bank-conflict-free)
//   3. MLP 12->3->12 (relu, sigmoid), one lane per row
//   4. gate-mul IN PLACE, lane 0 issues OWN 6 KB bulk store, drains it
// Shared tables written redundantly by all warps (identical values;
// benign race, own-warp program order guarantees visibility).

#define NFEAT 188
#define NF4   47
#define R     8                    // rows per warp
#define WARPS 4
#define NTHREADS (WARPS * 32)
#define ROWS_BLK (WARPS * R)       // 32

// packed segment ids for the 4 features of each float4 position (0..46)
__device__ __constant__ unsigned int c_stab[47] = {
    0x00000000u,0x00000000u,0x00000000u,0x00000000u,0x00000000u,
    0x01010101u,0x02020101u,0x02020202u,0x02020202u,0x02020202u,
    0x02020202u,0x03020202u,0x03030303u,0x03030303u,0x03030303u,
    0x03030303u,0x04030303u,0x04040404u,0x05050504u,0x05050505u,
    0x05050505u,0x05050505u,0x05050505u,0x06060505u,0x06060606u,
    0x06060606u,0x06060606u,0x06060606u,0x07070606u,0x07070707u,
    0x08080808u,0x08080808u,0x08080808u,0x08080808u,0x08080808u,
    0x09090908u,0x09090909u,0x09090909u,0x09090909u,0x09090909u,
    0x0A0A0A09u,0x0B0A0A0Au,0x0B0B0B0Bu,0x0B0B0B0Bu,0x0B0B0B0Bu,
    0x0B0B0B0Bu,0x0B0B0B0Bu
};

__global__ __launch_bounds__(NTHREADS, 8)
void senet_kernel(const float* __restrict__ x,
                  const float* __restrict__ W1,   // [3,12]
                  const float* __restrict__ b1,   // [3]
                  const float* __restrict__ W2,   // [12,3]
                  const float* __restrict__ b2,   // [12]
                  float* __restrict__ out,
                  int B)
{
    __shared__ __align__(16) float sx[WARPS * R * NFEAT];   // 24064 B
    __shared__ __align__(8)  unsigned long long smbar[WARPS];
    __shared__ float        smeans[WARPS][R][12];
    __shared__ float        sgates[WARPS][R][13];
    __shared__ float        sw[88];
    __shared__ unsigned int sstab[47];

    const int lane = threadIdx.x & 31;
    const int w    = threadIdx.x >> 5;

    const long long row0 = (long long)blockIdx.x * ROWS_BLK + w * R;
    int rows = B - (int)row0;
    if (rows <= 0) return;                  // warp-uniform exit
    if (rows > R) rows = R;
    const unsigned int bytes = (unsigned int)(rows * NFEAT) * 4u;

    float* sxw = sx + w * (R * NFEAT);
    const unsigned int sdst = (unsigned int)__cvta_generic_to_shared(sxw);
    const unsigned int mb   = (unsigned int)__cvta_generic_to_shared(&smbar[w]);
    const char* gsrc = (const char*)(x + row0 * NFEAT);

    // ---- phase 0: own mbarrier + own 6 KB bulk load (lane 0 only) ----
    if (lane == 0) {
        asm volatile("mbarrier.init.shared.b64 [%0], 1;" :: "r"(mb) : "memory");
        asm volatile("fence.proxy.async.shared::cta;" ::: "memory");
        asm volatile("mbarrier.arrive.expect_tx.shared.b64 _, [%0], %1;"
                     :: "r"(mb), "r"(bytes) : "memory");
        asm volatile(
            "{\n\t.reg .b64 pol;\n\t"
            "createpolicy.fractional.L2::evict_first.b64 pol, 1.0;\n\t"
            "cp.async.bulk.shared::cluster.global.mbarrier::complete_tx::bytes.L2::cache_hint"
            " [%0], [%1], %2, [%3], pol;\n\t}"
            :: "r"(sdst), "l"(gsrc), "r"(bytes), "r"(mb) : "memory");
    }

    // stage tables while the load flies (all warps write identical values;
    // benign race -- each warp reads only what it wrote, post __syncwarp)
    for (int j = lane; j < 47; j += 32) sstab[j] = c_stab[j];
    for (int j = lane; j < 87; j += 32) {
        float v;
        if      (j < 36) v = __ldg(W1 + j);
        else if (j < 39) v = __ldg(b1 + (j - 36));
        else if (j < 75) v = __ldg(W2 + (j - 39));
        else             v = __ldg(b2 + (j - 75));
        sw[j] = v;
    }
    __syncwarp();

    // ---- wait for OWN tile (parity 0), whole warp ----
    {
        unsigned int done;
        asm volatile(
            "{\n\t.reg .pred p;\n\t"
            "mbarrier.try_wait.parity.acquire.cta.shared::cta.b64 p, [%1], 0;\n\t"
            "selp.b32 %0, 1, 0, p;\n\t}"
            : "=r"(done) : "r"(mb) : "memory");
        if (!done) {
            asm volatile(
                "{\n\t.reg .pred p;\n"
                "W_%=:\n\t"
                "mbarrier.try_wait.parity.acquire.cta.shared::cta.b64 p, [%0], 0, 0x989680;\n\t"
                "@p bra D_%=;\n\t"
                "bra.uni W_%=;\n"
                "D_%=:\n\t}"
                :: "r"(mb) : "memory");
        }
    }
    __syncwarp();

    // ---- phase 2: segment sums (balanced, bank-conflict-free) ----
    {
        const int rq = lane >> 2;
        const int sq = lane & 3;
        if (rq < rows) {
            const float* xr = sxw + rq * NFEAT + sq * 47;
            float a0 = 0.f, a1 = 0.f, a2 = 0.f;
            #pragma unroll
            for (int j = 0;  j < 20; ++j) a0 += xr[j];
            #pragma unroll
            for (int j = 20; j < 26; ++j) a1 += xr[j];
            #pragma unroll
            for (int j = 26; j < 47; ++j) a2 += xr[j];
            smeans[w][rq][3 * sq + 0] = a0 * (1.f / 20.f);
            smeans[w][rq][3 * sq + 1] = a1 * (1.f / 6.f);
            smeans[w][rq][3 * sq + 2] = a2 * (1.f / 21.f);
        }
    }
    __syncwarp();

    // ---- phase 3: tiny MLP, one lane per row ----
    if (lane < rows) {
        float m[12];
        #pragma unroll
        for (int k = 0; k < 12; ++k) m[k] = smeans[w][lane][k];
        float h[3];
        #pragma unroll
        for (int j = 0; j < 3; ++j) {
            float a = sw[36 + j];
            #pragma unroll
            for (int k = 0; k < 12; ++k) a += m[k] * sw[j * 12 + k];
            h[j] = fmaxf(a, 0.f);
        }
        #pragma unroll
        for (int s = 0; s < 12; ++s) {
            float a = sw[75 + s];
            #pragma unroll
            for (int j = 0; j < 3; ++j) a += h[j] * sw[39 + s * 3 + j];
            sgates[w][lane][s] = __fdividef(1.f, 1.f + __expf(-a));
        }
    }
    __syncwarp();

    // ---- phase 4: gate multiply IN PLACE (warp's own region) ----
    {
        float4* sxw4 = (float4*)sxw;
        const int n4 = rows * NF4;
        #pragma unroll 3
        for (int i = lane; i < n4; i += 32) {
            const int row = i / NF4;
            const int p   = i - row * NF4;
            const unsigned int sid = sstab[p];
            const float* gr = sgates[w][row];
            float4 v = sxw4[i];
            v.x *= gr[sid         & 255];
            v.y *= gr[(sid >> 8)  & 255];
            v.z *= gr[(sid >> 16) & 255];
            v.w *= gr[ sid >> 24       ];
            sxw4[i] = v;
        }
    }
    __syncwarp();   // warp's STS visible before its own bulk store

    // ---- phase 5: OWN 6 KB bulk store (evict_first); own drain ----
    if (lane == 0) {
        char* gdst = (char*)(out + row0 * NFEAT);
        asm volatile("fence.proxy.async.shared::cta;" ::: "memory");
        asm volatile(
            "{\n\t.reg .b64 pol;\n\t"
            "createpolicy.fractional.L2::evict_first.b64 pol, 1.0;\n\t"
            "cp.async.bulk.global.shared::cta.bulk_group.L2::cache_hint"
            " [%0], [%1], %2, pol;\n\t}"
            :: "l"(gdst), "r"(sdst), "r"(bytes) : "memory");
        asm volatile("cp.async.bulk.commit_group;" ::: "memory");
        asm volatile("cp.async.bulk.wait_group.read 0;" ::: "memory");
    }
}

extern "C" void kernel_launch(void* const* d_in, const int* in_sizes, int n_in,
                              void* d_out, int out_size)
{
    const float* x  = (const float*)d_in[0];
    const float* W1 = (const float*)d_in[1];
    const float* b1 = (const float*)d_in[2];
    const float* W2 = (const float*)d_in[3];
    const float* b2 = (const float*)d_in[4];
    float* out = (float*)d_out;

    const int B = in_sizes[0] / NFEAT;
    const int grid = (B + ROWS_BLK - 1) / ROWS_BLK;
    senet_kernel<<<grid, NTHREADS>>>(x, W1, b1, W2, b2, out, B);
}

// round 14
// speedup vs baseline: 1.0265x; 1.0265x over previous
#include <cuda_runtime.h>
#include <cuda_bf16.h>

// SENet gating: block-granular 24 KB TMA load + direct register stores.
// Each 128-thread block handles 32 rows:
//   1. thread 0 issues ONE cp.async.bulk (24 KB) gmem->smem (evict_first);
//      all threads parity-wait the mbarrier
//   2. per-warp: segment sums (lane = row*4+quarter, pattern (20,6,21) x 4,
//      balanced + bank-conflict-free) -> MLP 12->3->12
//   3. per-warp: LDS.128 -> gate-mul -> STG.128 (__stcs, evict-first)
//      straight to gmem. No second smem pass, no store drain: the warp
//      retires as soon as its stores issue -> faster block turnover.

#define NFEAT 188
#define NF4   47
#define R     8                    // rows per warp
#define WARPS 4
#define NTHREADS (WARPS * 32)
#define ROWS_BLK (WARPS * R)       // 32
#define TILE_F  (ROWS_BLK * NFEAT) // 6016 floats = 24064 B

// packed segment ids for the 4 features of each float4 position (0..46)
__device__ __constant__ unsigned int c_stab[47] = {
    0x00000000u,0x00000000u,0x00000000u,0x00000000u,0x00000000u,
    0x01010101u,0x02020101u,0x02020202u,0x02020202u,0x02020202u,
    0x02020202u,0x03020202u,0x03030303u,0x03030303u,0x03030303u,
    0x03030303u,0x04030303u,0x04040404u,0x05050504u,0x05050505u,
    0x05050505u,0x05050505u,0x05050505u,0x06060505u,0x06060606u,
    0x06060606u,0x06060606u,0x06060606u,0x07070606u,0x07070707u,
    0x08080808u,0x08080808u,0x08080808u,0x08080808u,0x08080808u,
    0x09090908u,0x09090909u,0x09090909u,0x09090909u,0x09090909u,
    0x0A0A0A09u,0x0B0A0A0Au,0x0B0B0B0Bu,0x0B0B0B0Bu,0x0B0B0B0Bu,
    0x0B0B0B0Bu,0x0B0B0B0Bu
};

__global__ __launch_bounds__(NTHREADS, 8)
void senet_kernel(const float* __restrict__ x,
                  const float* __restrict__ W1,   // [3,12]
                  const float* __restrict__ b1,   // [3]
                  const float* __restrict__ W2,   // [12,3]
                  const float* __restrict__ b2,   // [12]
                  float* __restrict__ out,
                  int B)
{
    __shared__ __align__(16) float sx[TILE_F];              // 24064 B
    __shared__ __align__(8)  unsigned long long smbar;
    __shared__ float        smeans[WARPS][R][12];
    __shared__ float        sgates[WARPS][R][13];
    __shared__ float        sw[88];
    __shared__ unsigned int sstab[47];

    const int tid  = threadIdx.x;
    const int lane = tid & 31;
    const int w    = tid >> 5;

    const long long brow0 = (long long)blockIdx.x * ROWS_BLK;
    int rows_blk = B - (int)brow0;
    if (rows_blk > ROWS_BLK) rows_blk = ROWS_BLK;
    const unsigned int bytes = (unsigned int)(rows_blk * NFEAT) * 4u;

    const unsigned int sdst = (unsigned int)__cvta_generic_to_shared(sx);
    const unsigned int mb   = (unsigned int)__cvta_generic_to_shared(&smbar);
    const char* gsrc = (const char*)(x + brow0 * NFEAT);

    // ---- phase 0: init barrier, stage tables; ONE 24 KB bulk load ----
    if (tid == 0) {
        asm volatile("mbarrier.init.shared.b64 [%0], 1;" :: "r"(mb) : "memory");
        asm volatile("fence.proxy.async.shared::cta;" ::: "memory");
        asm volatile("mbarrier.arrive.expect_tx.shared.b64 _, [%0], %1;"
                     :: "r"(mb), "r"(bytes) : "memory");
        asm volatile(
            "{\n\t.reg .b64 pol;\n\t"
            "createpolicy.fractional.L2::evict_first.b64 pol, 1.0;\n\t"
            "cp.async.bulk.shared::cluster.global.mbarrier::complete_tx::bytes.L2::cache_hint"
            " [%0], [%1], %2, [%3], pol;\n\t}"
            :: "r"(sdst), "l"(gsrc), "r"(bytes), "r"(mb) : "memory");
    }
    if (tid < 47) sstab[tid] = c_stab[tid];
    for (int j = tid; j < 87; j += NTHREADS) {
        float v;
        if      (j < 36) v = __ldg(W1 + j);
        else if (j < 39) v = __ldg(b1 + (j - 36));
        else if (j < 75) v = __ldg(W2 + (j - 39));
        else             v = __ldg(b2 + (j - 75));
        sw[j] = v;
    }
    __syncthreads();    // mbarrier.init + tables visible to all warps

    // ---- wait for tile (parity 0), every thread ----
    {
        unsigned int done;
        asm volatile(
            "{\n\t.reg .pred p;\n\t"
            "mbarrier.try_wait.parity.acquire.cta.shared::cta.b64 p, [%1], 0;\n\t"
            "selp.b32 %0, 1, 0, p;\n\t}"
            : "=r"(done) : "r"(mb) : "memory");
        if (!done) {
            asm volatile(
                "{\n\t.reg .pred p;\n"
                "W_%=:\n\t"
                "mbarrier.try_wait.parity.acquire.cta.shared::cta.b64 p, [%0], 0, 0x989680;\n\t"
                "@p bra D_%=;\n\t"
                "bra.uni W_%=;\n"
                "D_%=:\n\t}"
                :: "r"(mb) : "memory");
        }
    }
    __syncwarp();

    // per-warp row count / region
    int rows = rows_blk - w * R;
    if (rows < 0) rows = 0;
    if (rows > R) rows = R;
    float* sxw = sx + w * (R * NFEAT);

    if (rows > 0) {
        // ---- phase 2: segment sums (balanced, bank-conflict-free) ----
        {
            const int rq = lane >> 2;
            const int sq = lane & 3;
            if (rq < rows) {
                const float* xr = sxw + rq * NFEAT + sq * 47;
                float a0 = 0.f, a1 = 0.f, a2 = 0.f;
                #pragma unroll
                for (int j = 0;  j < 20; ++j) a0 += xr[j];
                #pragma unroll
                for (int j = 20; j < 26; ++j) a1 += xr[j];
                #pragma unroll
                for (int j = 26; j < 47; ++j) a2 += xr[j];
                smeans[w][rq][3 * sq + 0] = a0 * (1.f / 20.f);
                smeans[w][rq][3 * sq + 1] = a1 * (1.f / 6.f);
                smeans[w][rq][3 * sq + 2] = a2 * (1.f / 21.f);
            }
        }
        __syncwarp();

        // ---- phase 3: tiny MLP, one lane per row ----
        if (lane < rows) {
            float m[12];
            #pragma unroll
            for (int k = 0; k < 12; ++k) m[k] = smeans[w][lane][k];
            float h[3];
            #pragma unroll
            for (int j = 0; j < 3; ++j) {
                float a = sw[36 + j];
                #pragma unroll
                for (int k = 0; k < 12; ++k) a += m[k] * sw[j * 12 + k];
                h[j] = fmaxf(a, 0.f);
            }
            #pragma unroll
            for (int s = 0; s < 12; ++s) {
                float a = sw[75 + s];
                #pragma unroll
                for (int j = 0; j < 3; ++j) a += h[j] * sw[39 + s * 3 + j];
                sgates[w][lane][s] = __fdividef(1.f, 1.f + __expf(-a));
            }
        }
        __syncwarp();

        // ---- phase 4: gate-mul -> DIRECT streaming store to gmem ----
        {
            const float4* sxw4 = (const float4*)sxw;
            float4* gout = (float4*)(out + (brow0 + w * R) * NFEAT);
            const int n4 = rows * NF4;
            #pragma unroll 3
            for (int i = lane; i < n4; i += 32) {
                const int row = i / NF4;
                const int p   = i - row * NF4;
                const unsigned int sid = sstab[p];
                const float* gr = sgates[w][row];
                float4 v = sxw4[i];
                v.x *= gr[sid         & 255];
                v.y *= gr[(sid >> 8)  & 255];
                v.z *= gr[(sid >> 16) & 255];
                v.w *= gr[ sid >> 24       ];
                __stcs(&gout[i], v);
            }
        }
        // no drain: warp retires as soon as its stores issue
    }
}

extern "C" void kernel_launch(void* const* d_in, const int* in_sizes, int n_in,
                              void* d_out, int out_size)
{
    const float* x  = (const float*)d_in[0];
    const float* W1 = (const float*)d_in[1];
    const float* b1 = (const float*)d_in[2];
    const float* W2 = (const float*)d_in[3];
    const float* b2 = (const float*)d_in[4];
    float* out = (float*)d_out;

    const int B = in_sizes[0] / NFEAT;
    const int grid = (B + ROWS_BLK - 1) / ROWS_BLK;
    senet_kernel<<<grid, NTHREADS>>>(x, W1, b1, W2, b2, out, B);
}

// round 15
// speedup vs baseline: 1.0297x; 1.0031x over previous
#include <cuda_runtime.h>
#include <cuda_bf16.h>

// SENet gating: block-granular 21 KB TMA load + direct register stores,
// 9 blocks/SM. Each 128-thread block handles 28 rows (R=7 per warp):
//   1. thread 0 issues ONE cp.async.bulk gmem->smem (evict_first);
//      all threads parity-wait the mbarrier
//   2. per-warp: segment sums (lane = row*4+quarter, pattern (20,6,21) x 4)
//   3. MLP 12->3->12, one lane per row (reads smeans directly; low regs)
//   4. per-warp: LDS.128 -> gate-mul -> __stcs STG.128 straight to gmem;
//      no second smem pass, no drain -> fast block turnover

#define NFEAT 188
#define NF4   47
#define R     7                    // rows per warp
#define WARPS 4
#define NTHREADS (WARPS * 32)
#define ROWS_BLK (WARPS * R)       // 28
#define TILE_F  (ROWS_BLK * NFEAT) // 5264 floats = 21056 B

// packed segment ids for the 4 features of each float4 position (0..46)
__device__ __constant__ unsigned int c_stab[47] = {
    0x00000000u,0x00000000u,0x00000000u,0x00000000u,0x00000000u,
    0x01010101u,0x02020101u,0x02020202u,0x02020202u,0x02020202u,
    0x02020202u,0x03020202u,0x03030303u,0x03030303u,0x03030303u,
    0x03030303u,0x04030303u,0x04040404u,0x05050504u,0x05050505u,
    0x05050505u,0x05050505u,0x05050505u,0x06060505u,0x06060606u,
    0x06060606u,0x06060606u,0x06060606u,0x07070606u,0x07070707u,
    0x08080808u,0x08080808u,0x08080808u,0x08080808u,0x08080808u,
    0x09090908u,0x09090909u,0x09090909u,0x09090909u,0x09090909u,
    0x0A0A0A09u,0x0B0A0A0Au,0x0B0B0B0Bu,0x0B0B0B0Bu,0x0B0B0B0Bu,
    0x0B0B0B0Bu,0x0B0B0B0Bu
};

__global__ __launch_bounds__(NTHREADS, 9)
void senet_kernel(const float* __restrict__ x,
                  const float* __restrict__ W1,   // [3,12]
                  const float* __restrict__ b1,   // [3]
                  const float* __restrict__ W2,   // [12,3]
                  const float* __restrict__ b2,   // [12]
                  float* __restrict__ out,
                  int B)
{
    __shared__ __align__(16) float sx[TILE_F];              // 21056 B
    __shared__ __align__(8)  unsigned long long smbar;
    __shared__ float        smeans[WARPS][R][12];
    __shared__ float        sgates[WARPS][R][13];
    __shared__ float        sw[88];
    __shared__ unsigned int sstab[47];

    const int tid  = threadIdx.x;
    const int lane = tid & 31;
    const int w    = tid >> 5;

    const long long brow0 = (long long)blockIdx.x * ROWS_BLK;
    int rows_blk = B - (int)brow0;
    if (rows_blk > ROWS_BLK) rows_blk = ROWS_BLK;
    const unsigned int bytes = (unsigned int)(rows_blk * NFEAT) * 4u;

    const unsigned int sdst = (unsigned int)__cvta_generic_to_shared(sx);
    const unsigned int mb   = (unsigned int)__cvta_generic_to_shared(&smbar);
    const char* gsrc = (const char*)(x + brow0 * NFEAT);

    // ---- phase 0: init barrier, stage tables; ONE bulk load ----
    if (tid == 0) {
        asm volatile("mbarrier.init.shared.b64 [%0], 1;" :: "r"(mb) : "memory");
        asm volatile("fence.proxy.async.shared::cta;" ::: "memory");
        asm volatile("mbarrier.arrive.expect_tx.shared.b64 _, [%0], %1;"
                     :: "r"(mb), "r"(bytes) : "memory");
        asm volatile(
            "{\n\t.reg .b64 pol;\n\t"
            "createpolicy.fractional.L2::evict_first.b64 pol, 1.0;\n\t"
            "cp.async.bulk.shared::cluster.global.mbarrier::complete_tx::bytes.L2::cache_hint"
            " [%0], [%1], %2, [%3], pol;\n\t}"
            :: "r"(sdst), "l"(gsrc), "r"(bytes), "r"(mb) : "memory");
    }
    if (tid < 47) sstab[tid] = c_stab[tid];
    for (int j = tid; j < 87; j += NTHREADS) {
        float v;
        if      (j < 36) v = __ldg(W1 + j);
        else if (j < 39) v = __ldg(b1 + (j - 36));
        else if (j < 75) v = __ldg(W2 + (j - 39));
        else             v = __ldg(b2 + (j - 75));
        sw[j] = v;
    }
    __syncthreads();    // mbarrier.init + tables visible to all warps

    // ---- wait for tile (parity 0), every thread ----
    {
        unsigned int done;
        asm volatile(
            "{\n\t.reg .pred p;\n\t"
            "mbarrier.try_wait.parity.acquire.cta.shared::cta.b64 p, [%1], 0;\n\t"
            "selp.b32 %0, 1, 0, p;\n\t}"
            : "=r"(done) : "r"(mb) : "memory");
        if (!done) {
            asm volatile(
                "{\n\t.reg .pred p;\n"
                "W_%=:\n\t"
                "mbarrier.try_wait.parity.acquire.cta.shared::cta.b64 p, [%0], 0, 0x989680;\n\t"
                "@p bra D_%=;\n\t"
                "bra.uni W_%=;\n"
                "D_%=:\n\t}"
                :: "r"(mb) : "memory");
        }
    }
    __syncwarp();

    // per-warp row count / region
    int rows = rows_blk - w * R;
    if (rows < 0) rows = 0;
    if (rows > R) rows = R;
    float* sxw = sx + w * (R * NFEAT);

    if (rows > 0) {
        // ---- phase 2: segment sums (balanced, bank-conflict-free) ----
        {
            const int rq = lane >> 2;       // 0..7; rq==7 idle (R=7)
            const int sq = lane & 3;
            if (rq < rows) {
                const float* xr = sxw + rq * NFEAT + sq * 47;
                float a0 = 0.f, a1 = 0.f, a2 = 0.f;
                #pragma unroll
                for (int j = 0;  j < 20; ++j) a0 += xr[j];
                #pragma unroll
                for (int j = 20; j < 26; ++j) a1 += xr[j];
                #pragma unroll
                for (int j = 26; j < 47; ++j) a2 += xr[j];
                smeans[w][rq][3 * sq + 0] = a0 * (1.f / 20.f);
                smeans[w][rq][3 * sq + 1] = a1 * (1.f / 6.f);
                smeans[w][rq][3 * sq + 2] = a2 * (1.f / 21.f);
            }
        }
        __syncwarp();

        // ---- phase 3: tiny MLP, one lane per row (means read from smem) ----
        if (lane < rows) {
            const float* mp = smeans[w][lane];
            float h[3];
            #pragma unroll
            for (int j = 0; j < 3; ++j) {
                float a = sw[36 + j];
                #pragma unroll
                for (int k = 0; k < 12; ++k) a += mp[k] * sw[j * 12 + k];
                h[j] = fmaxf(a, 0.f);
            }
            #pragma unroll
            for (int s = 0; s < 12; ++s) {
                float a = sw[75 + s];
                #pragma unroll
                for (int j = 0; j < 3; ++j) a += h[j] * sw[39 + s * 3 + j];
                sgates[w][lane][s] = __fdividef(1.f, 1.f + __expf(-a));
            }
        }
        __syncwarp();

        // ---- phase 4: gate-mul -> DIRECT streaming store to gmem ----
        {
            const float4* sxw4 = (const float4*)sxw;
            float4* gout = (float4*)(out + (brow0 + w * R) * NFEAT);
            const int n4 = rows * NF4;
            #pragma unroll 3
            for (int i = lane; i < n4; i += 32) {
                const int row = i / NF4;
                const int p   = i - row * NF4;
                const unsigned int sid = sstab[p];
                const float* gr = sgates[w][row];
                float4 v = sxw4[i];
                v.x *= gr[sid         & 255];
                v.y *= gr[(sid >> 8)  & 255];
                v.z *= gr[(sid >> 16) & 255];
                v.w *= gr[ sid >> 24       ];
                __stcs(&gout[i], v);
            }
        }
        // no drain: warp retires as soon as its stores issue
    }
}

extern "C" void kernel_launch(void* const* d_in, const int* in_sizes, int n_in,
                              void* d_out, int out_size)
{
    const float* x  = (const float*)d_in[0];
    const float* W1 = (const float*)d_in[1];
    const float* b1 = (const float*)d_in[2];
    const float* W2 = (const float*)d_in[3];
    const float* b2 = (const float*)d_in[4];
    float* out = (float*)d_out;

    const int B = in_sizes[0] / NFEAT;
    const int grid = (B + ROWS_BLK - 1) / ROWS_BLK;
    senet_kernel<<<grid, NTHREADS>>>(x, W1, b1, W2, b2, out, B);
}

// round 16
// speedup vs baseline: 1.0303x; 1.0006x over previous
#include <cuda_runtime.h>
#include <cuda_bf16.h>

// SENet gating: block-granular 18 KB TMA load + direct register stores,
// 10 blocks/SM. Each 128-thread block handles 24 rows (R=6 per warp):
//   1. thread 0 issues ONE cp.async.bulk gmem->smem (evict_first);
//      all threads parity-wait the mbarrier
//   2. per-warp: segment sums (lane = row*4+quarter, pattern (20,6,21) x 4)
//   3. MLP 12->3->12, one lane per row (means read from smem; low regs)
//   4. per-warp: LDS.128 -> gate-mul -> __stcs STG.128 straight to gmem;
//      no second smem pass, no drain -> fast block turnover

#define NFEAT 188
#define NF4   47
#define R     6                    // rows per warp
#define WARPS 4
#define NTHREADS (WARPS * 32)
#define ROWS_BLK (WARPS * R)       // 24
#define TILE_F  (ROWS_BLK * NFEAT) // 4512 floats = 18048 B

// packed segment ids for the 4 features of each float4 position (0..46)
__device__ __constant__ unsigned int c_stab[47] = {
    0x00000000u,0x00000000u,0x00000000u,0x00000000u,0x00000000u,
    0x01010101u,0x02020101u,0x02020202u,0x02020202u,0x02020202u,
    0x02020202u,0x03020202u,0x03030303u,0x03030303u,0x03030303u,
    0x03030303u,0x04030303u,0x04040404u,0x05050504u,0x05050505u,
    0x05050505u,0x05050505u,0x05050505u,0x06060505u,0x06060606u,
    0x06060606u,0x06060606u,0x06060606u,0x07070606u,0x07070707u,
    0x08080808u,0x08080808u,0x08080808u,0x08080808u,0x08080808u,
    0x09090908u,0x09090909u,0x09090909u,0x09090909u,0x09090909u,
    0x0A0A0A09u,0x0B0A0A0Au,0x0B0B0B0Bu,0x0B0B0B0Bu,0x0B0B0B0Bu,
    0x0B0B0B0Bu,0x0B0B0B0Bu
};

__global__ __launch_bounds__(NTHREADS, 10)
void senet_kernel(const float* __restrict__ x,
                  const float* __restrict__ W1,   // [3,12]
                  const float* __restrict__ b1,   // [3]
                  const float* __restrict__ W2,   // [12,3]
                  const float* __restrict__ b2,   // [12]
                  float* __restrict__ out,
                  int B)
{
    __shared__ __align__(16) float sx[TILE_F];              // 18048 B
    __shared__ __align__(8)  unsigned long long smbar;
    __shared__ float        smeans[WARPS][R][12];
    __shared__ float        sgates[WARPS][R][13];
    __shared__ float        sw[88];
    __shared__ unsigned int sstab[47];

    const int tid  = threadIdx.x;
    const int lane = tid & 31;
    const int w    = tid >> 5;

    const long long brow0 = (long long)blockIdx.x * ROWS_BLK;
    int rows_blk = B - (int)brow0;
    if (rows_blk > ROWS_BLK) rows_blk = ROWS_BLK;
    const unsigned int bytes = (unsigned int)(rows_blk * NFEAT) * 4u;

    const unsigned int sdst = (unsigned int)__cvta_generic_to_shared(sx);
    const unsigned int mb   = (unsigned int)__cvta_generic_to_shared(&smbar);
    const char* gsrc = (const char*)(x + brow0 * NFEAT);

    // ---- phase 0: init barrier, stage tables; ONE bulk load ----
    if (tid == 0) {
        asm volatile("mbarrier.init.shared.b64 [%0], 1;" :: "r"(mb) : "memory");
        asm volatile("fence.proxy.async.shared::cta;" ::: "memory");
        asm volatile("mbarrier.arrive.expect_tx.shared.b64 _, [%0], %1;"
                     :: "r"(mb), "r"(bytes) : "memory");
        asm volatile(
            "{\n\t.reg .b64 pol;\n\t"
            "createpolicy.fractional.L2::evict_first.b64 pol, 1.0;\n\t"
            "cp.async.bulk.shared::cluster.global.mbarrier::complete_tx::bytes.L2::cache_hint"
            " [%0], [%1], %2, [%3], pol;\n\t}"
            :: "r"(sdst), "l"(gsrc), "r"(bytes), "r"(mb) : "memory");
    }
    if (tid < 47) sstab[tid] = c_stab[tid];
    for (int j = tid; j < 87; j += NTHREADS) {
        float v;
        if      (j < 36) v = __ldg(W1 + j);
        else if (j < 39) v = __ldg(b1 + (j - 36));
        else if (j < 75) v = __ldg(W2 + (j - 39));
        else             v = __ldg(b2 + (j - 75));
        sw[j] = v;
    }
    __syncthreads();    // mbarrier.init + tables visible to all warps

    // ---- wait for tile (parity 0), every thread ----
    {
        unsigned int done;
        asm volatile(
            "{\n\t.reg .pred p;\n\t"
            "mbarrier.try_wait.parity.acquire.cta.shared::cta.b64 p, [%1], 0;\n\t"
            "selp.b32 %0, 1, 0, p;\n\t}"
            : "=r"(done) : "r"(mb) : "memory");
        if (!done) {
            asm volatile(
                "{\n\t.reg .pred p;\n"
                "W_%=:\n\t"
                "mbarrier.try_wait.parity.acquire.cta.shared::cta.b64 p, [%0], 0, 0x989680;\n\t"
                "@p bra D_%=;\n\t"
                "bra.uni W_%=;\n"
                "D_%=:\n\t}"
                :: "r"(mb) : "memory");
        }
    }
    __syncwarp();

    // per-warp row count / region
    int rows = rows_blk - w * R;
    if (rows < 0) rows = 0;
    if (rows > R) rows = R;
    float* sxw = sx + w * (R * NFEAT);

    if (rows > 0) {
        // ---- phase 2: segment sums (balanced, bank-conflict-free) ----
        {
            const int rq = lane >> 2;       // 0..7; rq >= 6 idle (R=6)
            const int sq = lane & 3;
            if (rq < rows) {
                const float* xr = sxw + rq * NFEAT + sq * 47;
                float a0 = 0.f, a1 = 0.f, a2 = 0.f;
                #pragma unroll
                for (int j = 0;  j < 20; ++j) a0 += xr[j];
                #pragma unroll
                for (int j = 20; j < 26; ++j) a1 += xr[j];
                #pragma unroll
                for (int j = 26; j < 47; ++j) a2 += xr[j];
                smeans[w][rq][3 * sq + 0] = a0 * (1.f / 20.f);
                smeans[w][rq][3 * sq + 1] = a1 * (1.f / 6.f);
                smeans[w][rq][3 * sq + 2] = a2 * (1.f / 21.f);
            }
        }
        __syncwarp();

        // ---- phase 3: tiny MLP, one lane per row (means read from smem) ----
        if (lane < rows) {
            const float* mp = smeans[w][lane];
            float h[3];
            #pragma unroll
            for (int j = 0; j < 3; ++j) {
                float a = sw[36 + j];
                #pragma unroll
                for (int k = 0; k < 12; ++k) a += mp[k] * sw[j * 12 + k];
                h[j] = fmaxf(a, 0.f);
            }
            #pragma unroll
            for (int s = 0; s < 12; ++s) {
                float a = sw[75 + s];
                #pragma unroll
                for (int j = 0; j < 3; ++j) a += h[j] * sw[39 + s * 3 + j];
                sgates[w][lane][s] = __fdividef(1.f, 1.f + __expf(-a));
            }
        }
        __syncwarp();

        // ---- phase 4: gate-mul -> DIRECT streaming store to gmem ----
        {
            const float4* sxw4 = (const float4*)sxw;
            float4* gout = (float4*)(out + (brow0 + w * R) * NFEAT);
            const int n4 = rows * NF4;
            #pragma unroll 3
            for (int i = lane; i < n4; i += 32) {
                const int row = i / NF4;
                const int p   = i - row * NF4;
                const unsigned int sid = sstab[p];
                const float* gr = sgates[w][row];
                float4 v = sxw4[i];
                v.x *= gr[sid         & 255];
                v.y *= gr[(sid >> 8)  & 255];
                v.z *= gr[(sid >> 16) & 255];
                v.w *= gr[ sid >> 24       ];
                __stcs(&gout[i], v);
            }
        }
        // no drain: warp retires as soon as its stores issue
    }
}

extern "C" void kernel_launch(void* const* d_in, const int* in_sizes, int n_in,
                              void* d_out, int out_size)
{
    const float* x  = (const float*)d_in[0];
    const float* W1 = (const float*)d_in[1];
    const float* b1 = (const float*)d_in[2];
    const float* W2 = (const float*)d_in[3];
    const float* b2 = (const float*)d_in[4];
    float* out = (float*)d_out;

    const int B = in_sizes[0] / NFEAT;
    const int grid = (B + ROWS_BLK - 1) / ROWS_BLK;
    senet_kernel<<<grid, NTHREADS>>>(x, W1, b1, W2, b2, out, B);
}